// round 13
// baseline (speedup 1.0000x reference)
#include <cuda_runtime.h>

#define Bn   32
#define Nn   1024
#define MLc  3
#define HIDn 100
#define ODIM 147
#define CK   13
#define WP   16            // padded weight-row stride
#define WPAD (CK * WP)     // 208

// fused interior tile: 128 rows x 64 cols, block = 512 threads (16 warps)
#define TH_  128
#define TW_  64
#define IRH  140   // TH_ + 12
#define IRW  76
#define IRP  76
#define HRH  70    // IRH/2 rows per parity array
#define OSP  68    // output staging pitch (16B-aligned rows)

// fused dynamic smem layout (float offsets)
#define OFF_SE   0
#define OFF_SO   (HRH * IRP)          // 5320
#define OFF_SW   (2 * HRH * IRP)      // 10640
#define SMEM_FLOATS (OFF_SW + WPAD)   // 10848
#define SMEM_BYTES  (SMEM_FLOATS * 4) // 43392

// frame-path offsets (same buffer; max 8449 < 10848)
#define FOFF_SX  0
#define FOFF_SR  2416
#define FOFF_ST  4520
#define FOFF_W1  8140
#define FOFF_W2  8290
#define FOFF_KA  8440

#define NBX  16
#define NBY  8
#define NINT (NBX * NBY)     // 128 interior blocks

__device__ float g_w1[Bn][ODIM];
__device__ float g_w2[Bn][ODIM];
__device__ float g_W13p[Bn][WPAD];
__device__ float g_r[(size_t)Bn * Nn * Nn];   // full-image residual scratch

// ---------------------------------------------------------------------------
// Kernel 0: both MLPs (ILP-10 layer 2) + composite 13x13 (padded). 768 thr.
// ---------------------------------------------------------------------------
__global__ __launch_bounds__(768)
void mlp_kernel(const float* __restrict__ kA,
                const float* __restrict__ w1a, const float* __restrict__ b1a,
                const float* __restrict__ w2a, const float* __restrict__ b2a,
                const float* __restrict__ w1b, const float* __restrict__ b1b,
                const float* __restrict__ w2b, const float* __restrict__ b2b) {
    const int b = blockIdx.x;
    const int t = threadIdx.x;
    const int path = t / 384;
    const int s = t - path * 384;
    __shared__ float skA[9];
    __shared__ float h[2][HIDn];
    __shared__ float part[2][ODIM][2];
    __shared__ float sh1[ODIM];
    __shared__ float sh2[ODIM];

    if (t < 9) skA[t] = kA[b * 9 + t];
    __syncthreads();

    const float* W1 = path ? w1b : w1a;
    const float* B1 = path ? b1b : b1a;
    const float* W2 = path ? w2b : w2a;
    const float* B2 = path ? b2b : b2a;

    if (s < HIDn) {
        float acc = B1[s];
#pragma unroll
        for (int k = 0; k < 9; k++) acc += skA[k] * W1[k * HIDn + s];
        h[path][s] = fmaxf(acc, 0.f);
    }
    __syncthreads();

    {
        const int o = s >> 1, half = s & 1;
        if (o < ODIM) {
            const int k0 = half * 50;
            float a[10];
#pragma unroll
            for (int j = 0; j < 10; j++) a[j] = 0.f;
#pragma unroll
            for (int kk = 0; kk < 5; kk++)
#pragma unroll
                for (int j = 0; j < 10; j++)
                    a[j] += h[path][k0 + kk * 10 + j] * W2[(k0 + kk * 10 + j) * ODIM + o];
            float acc = (((a[0] + a[1]) + (a[2] + a[3])) + ((a[4] + a[5]) + (a[6] + a[7]))) + (a[8] + a[9]);
            if (half == 0) acc += B2[o];
            part[path][o][half] = acc;
        }
    }
    __syncthreads();

    if (t < 2 * ODIM) {
        int pp = t / ODIM, o = t - pp * ODIM;
        float acc = part[pp][o][0] + part[pp][o][1];
        if (pp) { sh2[o] = acc; g_w2[b][o] = acc; }
        else    { sh1[o] = acc; g_w1[b][o] = acc; }
    }
    __syncthreads();

    if (t < WPAD) {
        int u = t >> 4, v = t & 15;
        float acc = 0.f;
        if (v < CK) {
            int i0 = max(0, u - 6), i1 = min(6, u);
            int j0 = max(0, v - 6), j1 = min(6, v);
            for (int m = 0; m < MLc; m++)
                for (int i = i0; i <= i1; i++)
                    for (int j = j0; j <= j1; j++)
                        acc += sh2[m * 49 + i * 7 + j] * sh1[m * 49 + (u - i) * 7 + (v - j)];
        }
        g_W13p[b][t] = acc;
    }
}

// ---------------------------------------------------------------------------
// Kernel 1: r-pass. r = f - corr3(x, kA), full image -> g_r.
// grid (4, 64, Bn): tile 256 cols x 16 rows, block 256 (8 warps). DRAM-bound.
// ---------------------------------------------------------------------------
#define RPW 260   // sx pitch
__global__ __launch_bounds__(256)
void rpass_kernel(const float* __restrict__ x, const float* __restrict__ f,
                  const float* __restrict__ kA) {
    const int b  = blockIdx.z;
    const int y0 = blockIdx.y * 16;
    const int c0 = blockIdx.x * 256;
    const int tid = threadIdx.x;
    const int lane = tid & 31;
    const int wid  = tid >> 5;

    __shared__ float sx[18 * RPW];
    __shared__ float skA[9];
    if (tid < 9) skA[tid] = kA[b * 9 + tid];

    const float* xb = x + (size_t)b * Nn * Nn;
    const float* fb = f + (size_t)b * Nn * Nn;
    float*       rb = g_r + (size_t)b * Nn * Nn;

    // load x rows y0-1 .. y0+16, cols c0-1 .. c0+256 (18 x 258), zero-padded
#pragma unroll 1
    for (int u = wid; u < 18; u += 8) {
        int gy = y0 - 1 + u;
        bool rok = (gy >= 0 && gy < Nn);
        float* sp = &sx[u * RPW];
#pragma unroll 1
        for (int v = lane; v < 258; v += 32) {
            int gx = c0 - 1 + v;
            sp[v] = (rok && gx >= 0 && gx < Nn) ? xb[gy * Nn + gx] : 0.f;
        }
    }
    __syncthreads();

    float k0 = skA[0], k1 = skA[1], k2 = skA[2],
          k3 = skA[3], k4 = skA[4], k5 = skA[5],
          k6 = skA[6], k7 = skA[7], k8 = skA[8];
#pragma unroll 1
    for (int u = wid; u < 16; u += 8) {
        const float* gp = &fb[(y0 + u) * Nn + c0];
        float* rp = &rb[(y0 + u) * Nn + c0];
        const float* xp = &sx[(u + 1) * RPW + 1];
#pragma unroll 1
        for (int v = lane; v < 256; v += 32) {
            float acc = gp[v];
            acc -= k0 * xp[-RPW + v - 1];
            acc -= k1 * xp[-RPW + v];
            acc -= k2 * xp[-RPW + v + 1];
            acc -= k3 * xp[v - 1];
            acc -= k4 * xp[v];
            acc -= k5 * xp[v + 1];
            acc -= k6 * xp[RPW + v - 1];
            acc -= k7 * xp[RPW + v];
            acc -= k8 * xp[RPW + v + 1];
            rp[v] = acc;
        }
    }
}

// apply one 13-tap weight row (padded, base wp) to acc[8] using rv[0..19]
__device__ __forceinline__ void apply_row(const float* __restrict__ wp,
                                          const float rv[20], float acc[8]) {
    const float4* wq = reinterpret_cast<const float4*>(wp);
    float4 wa = wq[0];
#pragma unroll
    for (int k = 0; k < 8; k++) acc[k] = fmaf(wa.x, rv[0 + k], acc[k]);
#pragma unroll
    for (int k = 0; k < 8; k++) acc[k] = fmaf(wa.y, rv[1 + k], acc[k]);
#pragma unroll
    for (int k = 0; k < 8; k++) acc[k] = fmaf(wa.z, rv[2 + k], acc[k]);
#pragma unroll
    for (int k = 0; k < 8; k++) acc[k] = fmaf(wa.w, rv[3 + k], acc[k]);
    float4 wb = wq[1];
#pragma unroll
    for (int k = 0; k < 8; k++) acc[k] = fmaf(wb.x, rv[4 + k], acc[k]);
#pragma unroll
    for (int k = 0; k < 8; k++) acc[k] = fmaf(wb.y, rv[5 + k], acc[k]);
#pragma unroll
    for (int k = 0; k < 8; k++) acc[k] = fmaf(wb.z, rv[6 + k], acc[k]);
#pragma unroll
    for (int k = 0; k < 8; k++) acc[k] = fmaf(wb.w, rv[7 + k], acc[k]);
    float4 wc = wq[2];
#pragma unroll
    for (int k = 0; k < 8; k++) acc[k] = fmaf(wc.x, rv[8 + k], acc[k]);
#pragma unroll
    for (int k = 0; k < 8; k++) acc[k] = fmaf(wc.y, rv[9 + k], acc[k]);
#pragma unroll
    for (int k = 0; k < 8; k++) acc[k] = fmaf(wc.z, rv[10 + k], acc[k]);
#pragma unroll
    for (int k = 0; k < 8; k++) acc[k] = fmaf(wc.w, rv[11 + k], acc[k]);
    float w12 = wp[12];
#pragma unroll
    for (int k = 0; k < 8; k++) acc[k] = fmaf(w12, rv[12 + k], acc[k]);
}

__device__ __forceinline__ void load_rv(const float* __restrict__ p, float rv[20]) {
    const float4* q = reinterpret_cast<const float4*>(p);
#pragma unroll
    for (int m = 0; m < 5; m++) {
        float4 t = q[m];
        rv[4 * m + 0] = t.x; rv[4 * m + 1] = t.y;
        rv[4 * m + 2] = t.z; rv[4 * m + 3] = t.w;
    }
}

// ---------------------------------------------------------------------------
// Kernel 2: fused. grid (160, Bn), block 512, dynamic smem 43.4 KB.
// blockIdx.x < 128 -> interior 128x64 composite tile (reads g_r);
// else frame segment (exact two-stage on 3-px border).
// ---------------------------------------------------------------------------
__global__ __launch_bounds__(512, 2)
void fused_kernel(const float* __restrict__ x, const float* __restrict__ f,
                  const float* __restrict__ kA, float* __restrict__ out) {
    extern __shared__ __align__(16) float smem[];
    const int b   = blockIdx.y;
    const int tid = threadIdx.x;
    const int lane = tid & 31;
    const int wid  = tid >> 5;          // 0..15

    const float* xb = x + (size_t)b * Nn * Nn;
    const float* fb = f + (size_t)b * Nn * Nn;
    float*       ob = out + (size_t)b * Nn * Nn;

    if (blockIdx.x < NINT) {
        // ================= interior path =================
        const int bx = blockIdx.x & (NBX - 1), by = blockIdx.x >> 4;
        const int ty0 = by * TH_, tx0 = bx * TW_;
        const bool edge = (bx == 0) | (bx == NBX - 1) | (by == 0) | (by == NBY - 1);

        float* sE = smem + OFF_SE;
        float* sO = smem + OFF_SO;
        float* sW = smem + OFF_SW;

        if (tid < WPAD) sW[tid] = g_W13p[b][tid];

        const float* rbase = g_r + (size_t)b * Nn * Nn;

        // load r tile 140x76 (origin ty0-6, tx0-6) into parity-split smem
        if (!edge) {
#pragma unroll 1
            for (int u = wid; u < IRH; u += 16) {
                const float* gp = &rbase[(ty0 - 6 + u) * Nn + tx0 - 6];
                float* sp = ((u & 1) ? sO : sE) + (u >> 1) * IRP;
#pragma unroll
                for (int v = lane; v < IRW; v += 32) sp[v] = gp[v];
            }
        } else {
#pragma unroll 1
            for (int u = wid; u < IRH; u += 16) {
                int gy = ty0 - 6 + u;
                bool rok = (gy >= 0 && gy < Nn);
                float* sp = ((u & 1) ? sO : sE) + (u >> 1) * IRP;
#pragma unroll
                for (int v = lane; v < IRW; v += 32) {
                    int gx = tx0 - 6 + v;
                    sp[v] = (rok && gx >= 0 && gx < Nn)
                            ? rbase[gy * Nn + gx] : 0.f;
                }
            }
        }
        __syncthreads();

        // Stage C: paired rows. pr = (wid&1)*32 + lane (0..63), strip = wid>>1.
        const int pr = ((wid & 1) << 5) + lane;     // 0..63
        const int v0 = (wid >> 1) << 3;             // 0..56
        float acc0[8], acc1[8];
#pragma unroll
        for (int k = 0; k < 8; k++) { acc0[k] = 0.f; acc1[k] = 0.f; }
        const float* pe = &sE[pr * IRP + v0];
        const float* po = &sO[pr * IRP + v0];
        float rv[20];

        load_rv(pe, rv);
        apply_row(&sW[0], rv, acc0);
#pragma unroll 1
        for (int t = 0; t < 6; t++) {
            load_rv(po + t * IRP, rv);
            apply_row(&sW[(2 * t + 1) * WP], rv, acc0);
            apply_row(&sW[(2 * t) * WP], rv, acc1);
            load_rv(pe + (t + 1) * IRP, rv);
            apply_row(&sW[(2 * t + 2) * WP], rv, acc0);
            apply_row(&sW[(2 * t + 1) * WP], rv, acc1);
        }
        load_rv(po + 6 * IRP, rv);
        apply_row(&sW[12 * WP], rv, acc1);
        __syncthreads();                 // all sE/sO reads done

        // stage results into smem (rows 2pr, 2pr+1; pitch 68; spans sE..sO)
        {
            float* sG = smem;
            float4* o0 = reinterpret_cast<float4*>(&sG[(2 * pr) * OSP + v0]);
            float4* o1 = reinterpret_cast<float4*>(&sG[(2 * pr + 1) * OSP + v0]);
#pragma unroll
            for (int g = 0; g < 2; g++) {
                float4 a, c;
                a.x = acc0[4 * g]; a.y = acc0[4 * g + 1]; a.z = acc0[4 * g + 2]; a.w = acc0[4 * g + 3];
                c.x = acc1[4 * g]; c.y = acc1[4 * g + 1]; c.z = acc1[4 * g + 2]; c.w = acc1[4 * g + 3];
                o0[g] = a; o1[g] = c;
            }
        }
        __syncthreads();

        // store: out = x (global, coalesced) + G2 (smem); edges skip 3-px border
        const float* sG = smem;
        if (!edge) {
#pragma unroll 1
            for (int u = wid; u < TH_; u += 16) {
                const float* xp = &xb[(ty0 + u) * Nn + tx0];
                float* op = &ob[(ty0 + u) * Nn + tx0];
                const float* gp = &sG[u * OSP];
#pragma unroll
                for (int v = lane; v < TW_; v += 32) op[v] = xp[v] + gp[v];
            }
        } else {
#pragma unroll 1
            for (int u = wid; u < TH_; u += 16) {
                int gy = ty0 + u;
                if (gy < 3 || gy >= Nn - 3) continue;
                const float* xp = &xb[gy * Nn + tx0];
                float* op = &ob[gy * Nn + tx0];
                const float* gp = &sG[u * OSP];
#pragma unroll
                for (int v = lane; v < TW_; v += 32) {
                    int gx = tx0 + v;
                    if (gx >= 3 && gx < Nn - 3) op[v] = xp[v] + gp[v];
                }
            }
        }
        return;
    }

    // ================= frame path (exact two-stage, 3-px border) ============
    const int seg = blockIdx.x - NINT;
    int oy0, ox0, OH, OW;
    if (seg < 8)       { oy0 = 0;    OH = 3; ox0 = seg * 128;        OW = 128; }
    else if (seg < 16) { oy0 = 1021; OH = 3; ox0 = (seg - 8) * 128;  OW = 128; }
    else if (seg < 24) { ox0 = 0;    OW = 3; oy0 = 3 + (seg - 16) * 128; OH = min(128, 1021 - oy0); }
    else               { ox0 = 1021; OW = 3; oy0 = 3 + (seg - 24) * 128; OH = min(128, 1021 - oy0); }
    const int TH = OH + 6,  TW = OW + 6;
    const int RH = OH + 12, RW = OW + 12;
    const int XH = OH + 14, XW = OW + 14;

    float* sx = smem + FOFF_SX;
    float* sr = smem + FOFF_SR;
    float* st = smem + FOFF_ST;
    float* sw1 = smem + FOFF_W1;
    float* sw2 = smem + FOFF_W2;
    float* skA = smem + FOFF_KA;

    if (tid < ODIM) { sw1[tid] = g_w1[b][tid]; sw2[tid] = g_w2[b][tid]; }
    if (tid < 9) skA[tid] = kA[b * 9 + tid];
    __syncthreads();

    for (int p = tid; p < XH * XW; p += 512) {
        int i = p / XW, j = p % XW;
        int gy = oy0 - 7 + i, gx = ox0 - 7 + j;
        sx[p] = (gy >= 0 && gy < Nn && gx >= 0 && gx < Nn) ? xb[gy * Nn + gx] : 0.f;
    }
    __syncthreads();

    for (int p = tid; p < RH * RW; p += 512) {
        int i = p / RW, j = p % RW;
        int gy = oy0 - 6 + i, gx = ox0 - 6 + j;
        float v = 0.f;
        if (gy >= 0 && gy < Nn && gx >= 0 && gx < Nn) {
            v = fb[gy * Nn + gx];
#pragma unroll
            for (int a = 0; a < 3; a++)
#pragma unroll
                for (int c = 0; c < 3; c++)
                    v -= skA[a * 3 + c] * sx[(i + a) * XW + (j + c)];
        }
        sr[p] = v;
    }
    __syncthreads();

    const int TA = TH * TW;
    for (int p = tid; p < 3 * TA; p += 512) {
        int m = p / TA, q = p - m * TA;
        int i = q / TW, j = q % TW;
        int gy = oy0 - 3 + i, gx = ox0 - 3 + j;
        float v = 0.f;
        if (gy >= 0 && gy < Nn && gx >= 0 && gx < Nn) {
#pragma unroll
            for (int a = 0; a < 7; a++)
#pragma unroll
                for (int c = 0; c < 7; c++)
                    v += sw1[m * 49 + a * 7 + c] * sr[(i + a) * RW + (j + c)];
        }
        st[m * TA + q] = v;
    }
    __syncthreads();

    for (int p = tid; p < OH * OW; p += 512) {
        int y = p / OW, xc = p % OW;
        float v = sx[(y + 7) * XW + (xc + 7)];
#pragma unroll
        for (int m = 0; m < MLc; m++)
#pragma unroll
            for (int a = 0; a < 7; a++)
#pragma unroll
                for (int c = 0; c < 7; c++)
                    v += sw2[m * 49 + a * 7 + c] * st[m * TA + (y + a) * TW + (xc + c)];
        ob[(oy0 + y) * Nn + (ox0 + xc)] = v;
    }
}

// ---------------------------------------------------------------------------
extern "C" void kernel_launch(void* const* d_in, const int* in_sizes, int n_in,
                              void* d_out, int out_size) {
    const float* x      = (const float*)d_in[0];
    const float* f      = (const float*)d_in[1];
    const float* kA     = (const float*)d_in[2];
    const float* fc1_w1 = (const float*)d_in[3];
    const float* fc1_b1 = (const float*)d_in[4];
    const float* fc1_w2 = (const float*)d_in[5];
    const float* fc1_b2 = (const float*)d_in[6];
    const float* fc2_w1 = (const float*)d_in[7];
    const float* fc2_b1 = (const float*)d_in[8];
    const float* fc2_w2 = (const float*)d_in[9];
    const float* fc2_b2 = (const float*)d_in[10];
    float* out = (float*)d_out;

    cudaFuncSetAttribute(fused_kernel,
                         cudaFuncAttributeMaxDynamicSharedMemorySize, SMEM_BYTES);

    mlp_kernel<<<Bn, 768>>>(kA, fc1_w1, fc1_b1, fc1_w2, fc1_b2,
                            fc2_w1, fc2_b1, fc2_w2, fc2_b2);

    dim3 gr(4, 64, Bn);
    rpass_kernel<<<gr, 256>>>(x, f, kA);

    dim3 g(NINT + 32, Bn);
    fused_kernel<<<g, 512, SMEM_BYTES>>>(x, f, kA, out);
}

// round 14
// speedup vs baseline: 1.2573x; 1.2573x over previous
#include <cuda_runtime.h>

#define Bn   32
#define Nn   1024
#define MLc  3
#define HIDn 100
#define ODIM 147
#define CK   13
#define WP   16            // padded weight-row stride
#define WPAD (CK * WP)     // 208

// interior tile: 64x64, block = 512 threads (16 warps), 3 blocks/SM target
#define TSZ  64
#define IXS  78    // TSZ + 14
#define IXP  79
#define IRS  76    // TSZ + 12
#define IRP  76
#define HR   38    // IRS/2 rows per parity array

// dynamic smem layout (float offsets)
#define OFF_SX   0
#define OFF_SE   6164                 // 78*79 = 6162, +2 pad -> 16B aligned
#define OFF_SO   (OFF_SE + HR * IRP)  // 9052
#define OFF_SW   (OFF_SO + HR * IRP)  // 11940
#define SMEM_FLOATS (OFF_SW + WPAD)   // 12148
#define SMEM_BYTES  (SMEM_FLOATS * 4) // 48592

// frame-path offsets (same buffer; max 8449 < 12148)
#define FOFF_SX  0
#define FOFF_SR  2416
#define FOFF_ST  4520
#define FOFF_W1  8140
#define FOFF_W2  8290
#define FOFF_KA  8440

#define NTX  16
#define NINT (NTX * NTX)     // 256 interior blocks

__device__ float g_w1[Bn][ODIM];
__device__ float g_w2[Bn][ODIM];
__device__ float g_W13p[Bn][WPAD];

// ---------------------------------------------------------------------------
// Kernel 0: both MLPs (ILP-10 layer 2) + composite 13x13 (padded). 768 thr.
// ---------------------------------------------------------------------------
__global__ __launch_bounds__(768)
void mlp_kernel(const float* __restrict__ kA,
                const float* __restrict__ w1a, const float* __restrict__ b1a,
                const float* __restrict__ w2a, const float* __restrict__ b2a,
                const float* __restrict__ w1b, const float* __restrict__ b1b,
                const float* __restrict__ w2b, const float* __restrict__ b2b) {
    const int b = blockIdx.x;
    const int t = threadIdx.x;
    const int path = t / 384;
    const int s = t - path * 384;
    __shared__ float skA[9];
    __shared__ float h[2][HIDn];
    __shared__ float part[2][ODIM][2];
    __shared__ float sh1[ODIM];
    __shared__ float sh2[ODIM];

    if (t < 9) skA[t] = kA[b * 9 + t];
    __syncthreads();

    const float* W1 = path ? w1b : w1a;
    const float* B1 = path ? b1b : b1a;
    const float* W2 = path ? w2b : w2a;
    const float* B2 = path ? b2b : b2a;

    if (s < HIDn) {
        float acc = B1[s];
#pragma unroll
        for (int k = 0; k < 9; k++) acc += skA[k] * W1[k * HIDn + s];
        h[path][s] = fmaxf(acc, 0.f);
    }
    __syncthreads();

    {
        const int o = s >> 1, half = s & 1;
        if (o < ODIM) {
            const int k0 = half * 50;
            float a[10];
#pragma unroll
            for (int j = 0; j < 10; j++) a[j] = 0.f;
#pragma unroll
            for (int kk = 0; kk < 5; kk++)
#pragma unroll
                for (int j = 0; j < 10; j++)
                    a[j] += h[path][k0 + kk * 10 + j] * W2[(k0 + kk * 10 + j) * ODIM + o];
            float acc = (((a[0] + a[1]) + (a[2] + a[3])) + ((a[4] + a[5]) + (a[6] + a[7]))) + (a[8] + a[9]);
            if (half == 0) acc += B2[o];
            part[path][o][half] = acc;
        }
    }
    __syncthreads();

    if (t < 2 * ODIM) {
        int pp = t / ODIM, o = t - pp * ODIM;
        float acc = part[pp][o][0] + part[pp][o][1];
        if (pp) { sh2[o] = acc; g_w2[b][o] = acc; }
        else    { sh1[o] = acc; g_w1[b][o] = acc; }
    }
    __syncthreads();

    if (t < WPAD) {
        int u = t >> 4, v = t & 15;
        float acc = 0.f;
        if (v < CK) {
            int i0 = max(0, u - 6), i1 = min(6, u);
            int j0 = max(0, v - 6), j1 = min(6, v);
            for (int m = 0; m < MLc; m++)
                for (int i = i0; i <= i1; i++)
                    for (int j = j0; j <= j1; j++)
                        acc += sh2[m * 49 + i * 7 + j] * sh1[m * 49 + (u - i) * 7 + (v - j)];
        }
        g_W13p[b][t] = acc;
    }
}

// apply one 13-tap weight row (padded base wp) to acc[4] using rv[0..15]
__device__ __forceinline__ void apply_row4(const float* __restrict__ wp,
                                           const float rv[16], float acc[4]) {
    const float4* wq = reinterpret_cast<const float4*>(wp);
    float4 wa = wq[0];
#pragma unroll
    for (int k = 0; k < 4; k++) acc[k] = fmaf(wa.x, rv[0 + k], acc[k]);
#pragma unroll
    for (int k = 0; k < 4; k++) acc[k] = fmaf(wa.y, rv[1 + k], acc[k]);
#pragma unroll
    for (int k = 0; k < 4; k++) acc[k] = fmaf(wa.z, rv[2 + k], acc[k]);
#pragma unroll
    for (int k = 0; k < 4; k++) acc[k] = fmaf(wa.w, rv[3 + k], acc[k]);
    float4 wb = wq[1];
#pragma unroll
    for (int k = 0; k < 4; k++) acc[k] = fmaf(wb.x, rv[4 + k], acc[k]);
#pragma unroll
    for (int k = 0; k < 4; k++) acc[k] = fmaf(wb.y, rv[5 + k], acc[k]);
#pragma unroll
    for (int k = 0; k < 4; k++) acc[k] = fmaf(wb.z, rv[6 + k], acc[k]);
#pragma unroll
    for (int k = 0; k < 4; k++) acc[k] = fmaf(wb.w, rv[7 + k], acc[k]);
    float4 wc = wq[2];
#pragma unroll
    for (int k = 0; k < 4; k++) acc[k] = fmaf(wc.x, rv[8 + k], acc[k]);
#pragma unroll
    for (int k = 0; k < 4; k++) acc[k] = fmaf(wc.y, rv[9 + k], acc[k]);
#pragma unroll
    for (int k = 0; k < 4; k++) acc[k] = fmaf(wc.z, rv[10 + k], acc[k]);
#pragma unroll
    for (int k = 0; k < 4; k++) acc[k] = fmaf(wc.w, rv[11 + k], acc[k]);
    float w12 = wp[12];
#pragma unroll
    for (int k = 0; k < 4; k++) acc[k] = fmaf(w12, rv[12 + k], acc[k]);
}

__device__ __forceinline__ void load_rv16(const float* __restrict__ p, float rv[16]) {
    const float4* q = reinterpret_cast<const float4*>(p);
#pragma unroll
    for (int m = 0; m < 4; m++) {
        float4 t = q[m];
        rv[4 * m + 0] = t.x; rv[4 * m + 1] = t.y;
        rv[4 * m + 2] = t.z; rv[4 * m + 3] = t.w;
    }
}

// ---------------------------------------------------------------------------
// Fused kernel. grid (288, Bn), block 512, dynamic smem 48.6 KB, 3 blocks/SM.
// blockIdx.x < 256 -> interior 64x64 tile; else frame segment.
// ---------------------------------------------------------------------------
__global__ __launch_bounds__(512, 3)
void fused_kernel(const float* __restrict__ x, const float* __restrict__ f,
                  const float* __restrict__ kA, float* __restrict__ out) {
    extern __shared__ __align__(16) float smem[];
    const int b   = blockIdx.y;
    const int tid = threadIdx.x;
    const int lane = tid & 31;
    const int wid  = tid >> 5;          // 0..15

    const float* xb = x + (size_t)b * Nn * Nn;
    const float* fb = f + (size_t)b * Nn * Nn;
    float*       ob = out + (size_t)b * Nn * Nn;

    if (blockIdx.x < NINT) {
        // ================= interior path =================
        const int bx = blockIdx.x & (NTX - 1), by = blockIdx.x >> 4;
        const int ty0 = by * TSZ, tx0 = bx * TSZ;
        const bool edge = (bx == 0) | (bx == NTX - 1) | (by == 0) | (by == NTX - 1);

        float* sx = smem + OFF_SX;
        float* sE = smem + OFF_SE;
        float* sO = smem + OFF_SO;
        float* sW = smem + OFF_SW;

        if (tid < WPAD) sW[tid] = g_W13p[b][tid];
        __shared__ float skA[9];
        if (tid < 9) skA[tid] = kA[b * 9 + tid];

        if (!edge) {
            // Stage A: x region 78x78 (origin -7)
#pragma unroll 1
            for (int u = wid; u < IXS; u += 16) {
                const float* gp = &xb[(ty0 - 7 + u) * Nn + tx0 - 7];
                float* sp = &sx[u * IXP];
#pragma unroll
                for (int v = lane; v < IXS; v += 32) sp[v] = gp[v];
            }
            __syncthreads();
            // Stage B: r = f - corr3(x,kA), 76x76 (origin -6), parity-split
            float k0 = skA[0], k1 = skA[1], k2 = skA[2],
                  k3 = skA[3], k4 = skA[4], k5 = skA[5],
                  k6 = skA[6], k7 = skA[7], k8 = skA[8];
            float* dstBase = (wid & 1) ? sO : sE;    // u = wid+16t: parity fixed
#pragma unroll 1
            for (int u = wid; u < IRS; u += 16) {
                const float* gp = &fb[(ty0 - 6 + u) * Nn + tx0 - 6];
                const float* xp = &sx[(u + 1) * IXP + 1];
                float* sp = &dstBase[(u >> 1) * IRP];
#pragma unroll
                for (int v = lane; v < IRS; v += 32) {
                    float acc = gp[v];
                    acc -= k0 * xp[-IXP + v - 1];
                    acc -= k1 * xp[-IXP + v];
                    acc -= k2 * xp[-IXP + v + 1];
                    acc -= k3 * xp[v - 1];
                    acc -= k4 * xp[v];
                    acc -= k5 * xp[v + 1];
                    acc -= k6 * xp[IXP + v - 1];
                    acc -= k7 * xp[IXP + v];
                    acc -= k8 * xp[IXP + v + 1];
                    sp[v] = acc;
                }
            }
        } else {
#pragma unroll 1
            for (int u = wid; u < IXS; u += 16) {
                int gy = ty0 - 7 + u;
                bool rok = (gy >= 0 && gy < Nn);
                float* sp = &sx[u * IXP];
#pragma unroll
                for (int v = lane; v < IXS; v += 32) {
                    int gx = tx0 - 7 + v;
                    sp[v] = (rok && gx >= 0 && gx < Nn) ? xb[gy * Nn + gx] : 0.f;
                }
            }
            __syncthreads();
            float k0 = skA[0], k1 = skA[1], k2 = skA[2],
                  k3 = skA[3], k4 = skA[4], k5 = skA[5],
                  k6 = skA[6], k7 = skA[7], k8 = skA[8];
            float* dstBase = (wid & 1) ? sO : sE;
#pragma unroll 1
            for (int u = wid; u < IRS; u += 16) {
                int gy = ty0 - 6 + u;
                bool rok = (gy >= 0 && gy < Nn);
                float* sp = &dstBase[(u >> 1) * IRP];
                const float* xp = &sx[(u + 1) * IXP + 1];
#pragma unroll
                for (int v = lane; v < IRS; v += 32) {
                    int gx = tx0 - 6 + v;
                    float val = 0.f;
                    if (rok && gx >= 0 && gx < Nn) {
                        float acc = fb[gy * Nn + gx];
                        acc -= k0 * xp[-IXP + v - 1];
                        acc -= k1 * xp[-IXP + v];
                        acc -= k2 * xp[-IXP + v + 1];
                        acc -= k3 * xp[v - 1];
                        acc -= k4 * xp[v];
                        acc -= k5 * xp[v + 1];
                        acc -= k6 * xp[IXP + v - 1];
                        acc -= k7 * xp[IXP + v];
                        acc -= k8 * xp[IXP + v + 1];
                        val = acc;
                    }
                    sp[v] = val;
                }
            }
        }
        __syncthreads();

        // Stage C: paired rows, 4-wide strips.
        // pr = (wid<<1)+(lane>>4) in 0..31; v0 = (lane&15)*4 in 0..60.
        // Output rows ty0+2pr, ty0+2pr+1; r rows 2pr+u: even u -> sE[pr+u/2],
        // odd u -> sO[pr+(u-1)/2]. LDS.128 conflict-free; STG.128 coalesced.
        const int pr = (wid << 1) + (lane >> 4);
        const int v0 = (lane & 15) << 2;
        float acc0[4], acc1[4];
#pragma unroll
        for (int k = 0; k < 4; k++) { acc0[k] = 0.f; acc1[k] = 0.f; }
        const float* pe = &sE[pr * IRP + v0];
        const float* po = &sO[pr * IRP + v0];
        float rv[16];

        load_rv16(pe, rv);
        apply_row4(&sW[0], rv, acc0);
#pragma unroll 1
        for (int t = 0; t < 6; t++) {
            load_rv16(po + t * IRP, rv);
            apply_row4(&sW[(2 * t + 1) * WP], rv, acc0);
            apply_row4(&sW[(2 * t) * WP], rv, acc1);
            load_rv16(pe + (t + 1) * IRP, rv);
            apply_row4(&sW[(2 * t + 2) * WP], rv, acc0);
            apply_row4(&sW[(2 * t + 1) * WP], rv, acc1);
        }
        load_rv16(po + 6 * IRP, rv);
        apply_row4(&sW[12 * WP], rv, acc1);

        // direct store: coalesced (lanes 0-15 = contiguous 256B row segment)
        const int gy0 = ty0 + 2 * pr;
        const int gx0 = tx0 + v0;
        if (!edge) {
            const float4 xv0 = *reinterpret_cast<const float4*>(&xb[gy0 * Nn + gx0]);
            const float4 xv1 = *reinterpret_cast<const float4*>(&xb[(gy0 + 1) * Nn + gx0]);
            float4 q0, q1;
            q0.x = acc0[0] + xv0.x; q0.y = acc0[1] + xv0.y;
            q0.z = acc0[2] + xv0.z; q0.w = acc0[3] + xv0.w;
            q1.x = acc1[0] + xv1.x; q1.y = acc1[1] + xv1.y;
            q1.z = acc1[2] + xv1.z; q1.w = acc1[3] + xv1.w;
            *reinterpret_cast<float4*>(&ob[gy0 * Nn + gx0]) = q0;
            *reinterpret_cast<float4*>(&ob[(gy0 + 1) * Nn + gx0]) = q1;
        } else {
#pragma unroll
            for (int rr = 0; rr < 2; rr++) {
                int gy = gy0 + rr;
                if (gy < 3 || gy >= Nn - 3) continue;
#pragma unroll
                for (int k = 0; k < 4; k++) {
                    int gx = gx0 + k;
                    if (gx >= 3 && gx < Nn - 3) {
                        float av = rr ? acc1[k] : acc0[k];
                        ob[gy * Nn + gx] = xb[gy * Nn + gx] + av;
                    }
                }
            }
        }
        return;
    }

    // ================= frame path (exact two-stage, 3-px border) ============
    const int seg = blockIdx.x - NINT;
    int oy0, ox0, OH, OW;
    if (seg < 8)       { oy0 = 0;    OH = 3; ox0 = seg * 128;        OW = 128; }
    else if (seg < 16) { oy0 = 1021; OH = 3; ox0 = (seg - 8) * 128;  OW = 128; }
    else if (seg < 24) { ox0 = 0;    OW = 3; oy0 = 3 + (seg - 16) * 128; OH = min(128, 1021 - oy0); }
    else               { ox0 = 1021; OW = 3; oy0 = 3 + (seg - 24) * 128; OH = min(128, 1021 - oy0); }
    const int TH = OH + 6,  TW = OW + 6;
    const int RH = OH + 12, RW = OW + 12;
    const int XH = OH + 14, XW = OW + 14;

    float* sx = smem + FOFF_SX;
    float* sr = smem + FOFF_SR;
    float* st = smem + FOFF_ST;
    float* sw1 = smem + FOFF_W1;
    float* sw2 = smem + FOFF_W2;
    float* skA = smem + FOFF_KA;

    if (tid < ODIM) { sw1[tid] = g_w1[b][tid]; sw2[tid] = g_w2[b][tid]; }
    if (tid < 9) skA[tid] = kA[b * 9 + tid];
    __syncthreads();

    for (int p = tid; p < XH * XW; p += 512) {
        int i = p / XW, j = p % XW;
        int gy = oy0 - 7 + i, gx = ox0 - 7 + j;
        sx[p] = (gy >= 0 && gy < Nn && gx >= 0 && gx < Nn) ? xb[gy * Nn + gx] : 0.f;
    }
    __syncthreads();

    for (int p = tid; p < RH * RW; p += 512) {
        int i = p / RW, j = p % RW;
        int gy = oy0 - 6 + i, gx = ox0 - 6 + j;
        float v = 0.f;
        if (gy >= 0 && gy < Nn && gx >= 0 && gx < Nn) {
            v = fb[gy * Nn + gx];
#pragma unroll
            for (int a = 0; a < 3; a++)
#pragma unroll
                for (int c = 0; c < 3; c++)
                    v -= skA[a * 3 + c] * sx[(i + a) * XW + (j + c)];
        }
        sr[p] = v;
    }
    __syncthreads();

    const int TA = TH * TW;
    for (int p = tid; p < 3 * TA; p += 512) {
        int m = p / TA, q = p - m * TA;
        int i = q / TW, j = q % TW;
        int gy = oy0 - 3 + i, gx = ox0 - 3 + j;
        float v = 0.f;
        if (gy >= 0 && gy < Nn && gx >= 0 && gx < Nn) {
#pragma unroll
            for (int a = 0; a < 7; a++)
#pragma unroll
                for (int c = 0; c < 7; c++)
                    v += sw1[m * 49 + a * 7 + c] * sr[(i + a) * RW + (j + c)];
        }
        st[m * TA + q] = v;
    }
    __syncthreads();

    for (int p = tid; p < OH * OW; p += 512) {
        int y = p / OW, xc = p % OW;
        float v = sx[(y + 7) * XW + (xc + 7)];
#pragma unroll
        for (int m = 0; m < MLc; m++)
#pragma unroll
            for (int a = 0; a < 7; a++)
#pragma unroll
                for (int c = 0; c < 7; c++)
                    v += sw2[m * 49 + a * 7 + c] * st[m * TA + (y + a) * TW + (xc + c)];
        ob[(oy0 + y) * Nn + (ox0 + xc)] = v;
    }
}

// ---------------------------------------------------------------------------
extern "C" void kernel_launch(void* const* d_in, const int* in_sizes, int n_in,
                              void* d_out, int out_size) {
    const float* x      = (const float*)d_in[0];
    const float* f      = (const float*)d_in[1];
    const float* kA     = (const float*)d_in[2];
    const float* fc1_w1 = (const float*)d_in[3];
    const float* fc1_b1 = (const float*)d_in[4];
    const float* fc1_w2 = (const float*)d_in[5];
    const float* fc1_b2 = (const float*)d_in[6];
    const float* fc2_w1 = (const float*)d_in[7];
    const float* fc2_b1 = (const float*)d_in[8];
    const float* fc2_w2 = (const float*)d_in[9];
    const float* fc2_b2 = (const float*)d_in[10];
    float* out = (float*)d_out;

    cudaFuncSetAttribute(fused_kernel,
                         cudaFuncAttributeMaxDynamicSharedMemorySize, SMEM_BYTES);

    mlp_kernel<<<Bn, 768>>>(kA, fc1_w1, fc1_b1, fc1_w2, fc1_b2,
                            fc2_w1, fc2_b1, fc2_w2, fc2_b2);

    dim3 g(NINT + 32, Bn);
    fused_kernel<<<g, 512, SMEM_BYTES>>>(x, f, kA, out);
}